// round 1
// baseline (speedup 1.0000x reference)
#include <cuda_runtime.h>

#define N_ATOMS 50000
#define N_PAIRS 800000
#define N_EMB   128
#define N_DIST  100
#define N_HID   128
#define TPB     256

// Scratch: atom hidden features (atom_features @ W_cf + b_cf), 25.6 MB.
// __device__ global per allocation rules.
__device__ float g_afh[(size_t)N_ATOMS * N_HID];

// ---------- packed f32x2 helpers (full-rate fp32 on sm_103a) ----------
static __device__ __forceinline__ void ffma2(unsigned long long &acc,
                                             unsigned long long a,
                                             unsigned long long b) {
    asm("fma.rn.f32x2 %0, %1, %2, %0;" : "+l"(acc) : "l"(a), "l"(b));
}
static __device__ __forceinline__ unsigned long long mul2(unsigned long long a,
                                                          unsigned long long b) {
    unsigned long long r;
    asm("mul.rn.f32x2 %0, %1, %2;" : "=l"(r) : "l"(a), "l"(b));
    return r;
}
static __device__ __forceinline__ unsigned long long pack2(float lo, float hi) {
    unsigned long long r;
    asm("mov.b64 %0, {%1, %2};" : "=l"(r) : "f"(lo), "f"(hi));
    return r;
}
static __device__ __forceinline__ unsigned long long dup2(float v) {
    unsigned long long r;
    asm("mov.b64 %0, {%1, %1};" : "=l"(r) : "f"(v));
    return r;
}
static __device__ __forceinline__ void unpack2(unsigned long long p, float &lo, float &hi) {
    asm("mov.b64 {%0, %1}, %2;" : "=f"(lo), "=f"(hi) : "l"(p));
}

// Accurate-enough tanh: 2 MUFU ops (ex2 + rcp), ~1e-6 abs error.
// (tanh.approx.f32 would be 1 op but ~5e-4 abs error — too risky vs 1e-3 gate.)
static __device__ __forceinline__ float fast_tanh(float x) {
    float e = __expf(2.0f * x);
    return 1.0f - __fdividef(2.0f, e + 1.0f);
}

// =====================================================================
// Kernel 1: per 128-atom tile:
//   afh = atom_features @ W_cf + b_cf          -> g_afh
//   out = atom_features - tanh((b_df*afh) @ W_fc)
// Thread t owns row r=t>>1, 64 columns at cOff=(t&1)*64 (32 f32x2 accs).
// =====================================================================
__global__ void __launch_bounds__(TPB, 1) atoms_kernel(
    const float* __restrict__ atom_features,
    const float* __restrict__ W_cf,
    const float* __restrict__ W_fc,
    const float* __restrict__ b_cf,
    const float* __restrict__ b_df,
    float* __restrict__ out)
{
    extern __shared__ float smem[];
    float* bcf_s = smem;                 // 128
    float* bdf_s = smem + 128;           // 128
    float* A_s   = smem + 256;           // 128 x (stride 129)  atom_features tile
    float* W_s   = A_s + 128 * 129;      // 128 x 128           W_cf then W_fc
    float* M_s   = W_s + 128 * 128;      // 128 x (stride 130)  b_df*afh

    const int tid  = threadIdx.x;
    const int r    = tid >> 1;
    const int cOff = (tid & 1) << 6;
    const int base = blockIdx.x * 128;
    const int rows = min(128, N_ATOMS - base);

    if (tid < 128) { bcf_s[tid] = b_cf[tid]; bdf_s[tid] = b_df[tid]; }
    for (int idx = tid; idx < 128 * 128; idx += TPB) {
        int rr = idx >> 7, cc = idx & 127;
        A_s[rr * 129 + cc] = (rr < rows) ? atom_features[(size_t)(base + rr) * N_EMB + cc]
                                         : 0.0f;
        W_s[idx] = W_cf[idx];
    }
    __syncthreads();

    unsigned long long acc[32];
#pragma unroll
    for (int i = 0; i < 32; i++) acc[i] = pack2(bcf_s[cOff + 2 * i], bcf_s[cOff + 2 * i + 1]);

    for (int k = 0; k < 128; k++) {
        unsigned long long a2 = dup2(A_s[r * 129 + k]);
        const ulonglong2* wrow = (const ulonglong2*)(W_s + k * 128 + cOff);
#pragma unroll
        for (int q = 0; q < 16; q++) {
            ulonglong2 w = wrow[q];
            ffma2(acc[2 * q],     a2, w.x);
            ffma2(acc[2 * q + 1], a2, w.y);
        }
    }

    // write afh, then form M = b_df * afh (in regs)
    if (r < rows) {
        unsigned long long* arow =
            (unsigned long long*)(g_afh + (size_t)(base + r) * N_HID + cOff);
#pragma unroll
        for (int i = 0; i < 32; i++) arow[i] = acc[i];
    }
#pragma unroll
    for (int i = 0; i < 32; i++)
        acc[i] = mul2(acc[i], pack2(bdf_s[cOff + 2 * i], bdf_s[cOff + 2 * i + 1]));

    __syncthreads();  // all GEMM1 reads of W_s done before W_fc overwrite
    {
        unsigned long long* mrow = (unsigned long long*)(M_s + r * 130 + cOff);
#pragma unroll
        for (int i = 0; i < 32; i++) mrow[i] = acc[i];
    }
    for (int idx = tid; idx < 128 * 128; idx += TPB) W_s[idx] = W_fc[idx];
    __syncthreads();

#pragma unroll
    for (int i = 0; i < 32; i++) acc[i] = 0ULL;
    for (int k = 0; k < 128; k++) {
        unsigned long long a2 = dup2(M_s[r * 130 + k]);
        const ulonglong2* wrow = (const ulonglong2*)(W_s + k * 128 + cOff);
#pragma unroll
        for (int q = 0; q < 16; q++) {
            ulonglong2 w = wrow[q];
            ffma2(acc[2 * q],     a2, w.x);
            ffma2(acc[2 * q + 1], a2, w.y);
        }
    }

    if (r < rows) {
        float* orow = out + (size_t)(base + r) * N_EMB + cOff;
#pragma unroll
        for (int i = 0; i < 32; i++) {
            float lo, hi; unpack2(acc[i], lo, hi);
            orow[2 * i]     = A_s[r * 129 + cOff + 2 * i]     - fast_tanh(lo);
            orow[2 * i + 1] = A_s[r * 129 + cOff + 2 * i + 1] - fast_tanh(hi);
        }
    }
}

// =====================================================================
// Kernel 2: per 128-pair tile:
//   dh  = distance @ W_df + b_df
//   m   = dh * g_afh[j]                         (gather, L2-resident)
//   msg = tanh(m @ W_fc)
//   segment-sum msg over sorted i within tile, atomicAdd per distinct i
// =====================================================================
__global__ void __launch_bounds__(TPB, 1) pairs_kernel(
    const float* __restrict__ distance,
    const int*   __restrict__ dmi,
    const int*   __restrict__ dmj,
    const float* __restrict__ W_df,
    const float* __restrict__ W_fc,
    const float* __restrict__ b_df,
    float* __restrict__ out)
{
    extern __shared__ float smem[];
    int*   i_s   = (int*)smem;           // 128
    int*   j_s   = ((int*)smem) + 128;   // 128
    float* bdf_s = smem + 256;           // 128
    float* R1    = smem + 384;           // dist 128x(101) -> m/msg 128x(130)
    float* R2    = R1 + 128 * 130;       // W_df (100x128) -> W_fc (128x128)

    const int tid   = threadIdx.x;
    const int r     = tid >> 1;
    const int cOff  = (tid & 1) << 6;
    const int pbase = blockIdx.x * 128;

    if (tid < 128) {
        i_s[tid]   = dmi[pbase + tid];
        j_s[tid]   = dmj[pbase + tid];
        bdf_s[tid] = b_df[tid];
    }
    for (int idx = tid; idx < 128 * N_DIST; idx += TPB) {
        int rr = idx / N_DIST;
        int cc = idx - rr * N_DIST;
        R1[rr * 101 + cc] = distance[(size_t)pbase * N_DIST + idx];
        R2[idx]           = W_df[idx];   // 12800 contiguous elements
    }
    __syncthreads();

    // GEMM1: dh = dist @ W_df + b_df
    unsigned long long acc[32];
#pragma unroll
    for (int i = 0; i < 32; i++) acc[i] = pack2(bdf_s[cOff + 2 * i], bdf_s[cOff + 2 * i + 1]);

    for (int k = 0; k < N_DIST; k++) {
        unsigned long long a2 = dup2(R1[r * 101 + k]);
        const ulonglong2* wrow = (const ulonglong2*)(R2 + k * 128 + cOff);
#pragma unroll
        for (int q = 0; q < 16; q++) {
            ulonglong2 w = wrow[q];
            ffma2(acc[2 * q],     a2, w.x);
            ffma2(acc[2 * q + 1], a2, w.y);
        }
    }

    // m = dh * afh[j]  (gather; afh table is L2-resident at 25.6 MB)
    {
        const int j = j_s[r];
        const ulonglong2* arow = (const ulonglong2*)(g_afh + (size_t)j * N_HID + cOff);
#pragma unroll
        for (int q = 0; q < 16; q++) {
            ulonglong2 a = arow[q];
            acc[2 * q]     = mul2(acc[2 * q],     a.x);
            acc[2 * q + 1] = mul2(acc[2 * q + 1], a.y);
        }
    }
    __syncthreads();  // GEMM1 reads of R1/R2 complete
    {
        unsigned long long* mrow = (unsigned long long*)(R1 + r * 130 + cOff);
#pragma unroll
        for (int i = 0; i < 32; i++) mrow[i] = acc[i];
    }
    for (int idx = tid; idx < 128 * 128; idx += TPB) R2[idx] = W_fc[idx];
    __syncthreads();

    // GEMM2: pre = m @ W_fc
#pragma unroll
    for (int i = 0; i < 32; i++) acc[i] = 0ULL;
    for (int k = 0; k < N_HID; k++) {
        unsigned long long a2 = dup2(R1[r * 130 + k]);
        const ulonglong2* wrow = (const ulonglong2*)(R2 + k * 128 + cOff);
#pragma unroll
        for (int q = 0; q < 16; q++) {
            ulonglong2 w = wrow[q];
            ffma2(acc[2 * q],     a2, w.x);
            ffma2(acc[2 * q + 1], a2, w.y);
        }
    }
    __syncthreads();  // all reads of R1 (m) complete before msg overwrite

    // msg = tanh(pre) -> R1
    {
        float* mrow = R1 + r * 130 + cOff;
#pragma unroll
        for (int i = 0; i < 32; i++) {
            float lo, hi; unpack2(acc[i], lo, hi);
            mrow[2 * i]     = fast_tanh(lo);
            mrow[2 * i + 1] = fast_tanh(hi);
        }
    }
    __syncthreads();

    // Segmented reduction: i is globally sorted, so equal-i rows are
    // consecutive. 256 threads = 128 columns x 2 row-halves; one atomicAdd
    // per (segment-run, column). Branch is warp-uniform (i same across lanes).
    {
        const int c  = tid & 127;
        const int r0 = (tid >> 7) << 6;  // 0 or 64
        int   cur = i_s[r0];
        float sum = 0.0f;
        for (int rr = r0; rr < r0 + 64; rr++) {
            int ii = i_s[rr];
            if (ii != cur) {
                atomicAdd(out + (size_t)cur * N_EMB + c, sum);
                cur = ii;
                sum = 0.0f;
            }
            sum += R1[rr * 130 + c];
        }
        atomicAdd(out + (size_t)cur * N_EMB + c, sum);
    }
}

// =====================================================================
// Launch
// =====================================================================
extern "C" void kernel_launch(void* const* d_in, const int* in_sizes, int n_in,
                              void* d_out, int out_size)
{
    const float* atom_features = (const float*)d_in[0];
    const float* distance      = (const float*)d_in[1];
    // d_in[2] = atom_membership: unused by the reference computation
    const int*   dmi           = (const int*)d_in[3];
    const int*   dmj           = (const int*)d_in[4];
    const float* W_cf          = (const float*)d_in[5];
    const float* W_df          = (const float*)d_in[6];
    const float* W_fc          = (const float*)d_in[7];
    const float* b_cf          = (const float*)d_in[8];
    const float* b_df          = (const float*)d_in[9];
    float*       out           = (float*)d_out;

    const int smem12 = (256 + 128 * 129 + 128 * 128 + 128 * 130) * 4;  // 199168 B
    const int smem3  = (384 + 128 * 130 + 128 * 128) * 4;              // 133632 B

    cudaFuncSetAttribute(atoms_kernel, cudaFuncAttributeMaxDynamicSharedMemorySize, smem12);
    cudaFuncSetAttribute(pairs_kernel, cudaFuncAttributeMaxDynamicSharedMemorySize, smem3);

    // 1) afh + out init (out fully rewritten each call -> graph-replay safe)
    atoms_kernel<<<(N_ATOMS + 127) / 128, TPB, smem12>>>(
        atom_features, W_cf, W_fc, b_cf, b_df, out);

    // 2) pair pipeline + segment accumulation (same stream -> ordered)
    pairs_kernel<<<N_PAIRS / 128, TPB, smem3>>>(
        distance, dmi, dmj, W_df, W_fc, b_df, out);
}

// round 2
// speedup vs baseline: 1.9081x; 1.9081x over previous
#include <cuda_runtime.h>

#define N_ATOMS 50000
#define N_PAIRS 800000
#define N_EMB   128
#define N_DIST  100
#define N_HID   128
#define TPB     256

typedef unsigned long long ull;

// Scratch: atom hidden features (atom_features @ W_cf + b_cf), 25.6 MB.
__device__ float g_afh[(size_t)N_ATOMS * N_HID];

// ---------- packed f32x2 helpers (full-rate fp32 on sm_103a) ----------
static __device__ __forceinline__ void ffma2(ull &acc, ull a, ull b) {
    asm("fma.rn.f32x2 %0, %1, %2, %0;" : "+l"(acc) : "l"(a), "l"(b));
}
static __device__ __forceinline__ ull mul2(ull a, ull b) {
    ull r; asm("mul.rn.f32x2 %0, %1, %2;" : "=l"(r) : "l"(a), "l"(b)); return r;
}
static __device__ __forceinline__ ull pack2(float lo, float hi) {
    ull r; asm("mov.b64 %0, {%1, %2};" : "=l"(r) : "f"(lo), "f"(hi)); return r;
}
static __device__ __forceinline__ ull dup2(float v) {
    ull r; asm("mov.b64 %0, {%1, %1};" : "=l"(r) : "f"(v)); return r;
}
static __device__ __forceinline__ void unpack2(ull p, float &lo, float &hi) {
    asm("mov.b64 {%0, %1}, %2;" : "=f"(lo), "=f"(hi) : "l"(p));
}

// ~1e-6-accurate tanh from 2 MUFU ops.
static __device__ __forceinline__ float fast_tanh(float x) {
    float e = __expf(2.0f * x);
    return 1.0f - __fdividef(2.0f, e + 1.0f);
}

// Inner-product micro-kernel step: 8 rows (scalar broadcast from A, row
// stride SA) x 8 cols (2x LDS.128 from B row k), 32 FFMA2.
template<int SA>
static __device__ __forceinline__ void gemm_step(
    const float* __restrict__ Arow,   // A + r0*SA  (thread's first row)
    const float* __restrict__ Bk,     // Bs + k*128 + c0
    int k, ull acc[32])
{
    ull a2[8];
#pragma unroll
    for (int i = 0; i < 8; i++) a2[i] = dup2(Arow[i * SA + k]);
    ulonglong2 b01 = *(const ulonglong2*)(Bk);
    ulonglong2 b23 = *(const ulonglong2*)(Bk + 4);
#pragma unroll
    for (int i = 0; i < 8; i++) {
        ffma2(acc[i * 4 + 0], a2[i], b01.x);
        ffma2(acc[i * 4 + 1], a2[i], b01.y);
        ffma2(acc[i * 4 + 2], a2[i], b23.x);
        ffma2(acc[i * 4 + 3], a2[i], b23.y);
    }
}

// =====================================================================
// Kernel 1 (atoms): per 128-atom tile
//   afh = A @ W_cf + b_cf            -> g_afh
//   out = A - tanh((b_df*afh) @ W_fc)
// smem: Af[128][132], Ms[128][132], Bs[128][128], biases
// =====================================================================
__global__ void __launch_bounds__(TPB, 1) atoms_kernel(
    const float* __restrict__ atom_features,
    const float* __restrict__ W_cf,
    const float* __restrict__ W_fc,
    const float* __restrict__ b_cf,
    const float* __restrict__ b_df,
    float* __restrict__ out)
{
    extern __shared__ float smem[];
    float* bcf_s = smem;            // 128
    float* bdf_s = smem + 128;      // 128
    float* Af    = smem + 256;      // 128 x 132
    float* Ms    = Af + 128 * 132;  // 128 x 132
    float* Bs    = Ms + 128 * 132;  // 128 x 128

    const int tid = threadIdx.x;
    const int tx = tid & 15, ty = tid >> 4;
    const int c0 = tx * 8, r0 = ty * 8;
    const int base = blockIdx.x * 128;
    const int rows = min(128, N_ATOMS - base);

    if (tid < 128) { bcf_s[tid] = b_cf[tid]; bdf_s[tid] = b_df[tid]; }
    // A tile (zero-padded) + W_cf, float4 linear
    for (int idx = tid; idx < 128 * 32; idx += TPB) {
        int rr = idx >> 5, q = idx & 31;
        float4 v = make_float4(0.f, 0.f, 0.f, 0.f);
        if (rr < rows) v = ((const float4*)atom_features)[(size_t)(base + rr) * 32 + q];
        ((float4*)Af)[rr * 33 + q] = v;
        ((float4*)Bs)[idx] = ((const float4*)W_cf)[idx];
    }
    __syncthreads();

    ull acc[32];
    {   // bias init (same per row)
        ull b[4];
#pragma unroll
        for (int q = 0; q < 4; q++) b[q] = pack2(bcf_s[c0 + 2*q], bcf_s[c0 + 2*q + 1]);
#pragma unroll
        for (int i = 0; i < 8; i++)
#pragma unroll
            for (int q = 0; q < 4; q++) acc[i * 4 + q] = b[q];
    }
    {
        const float* Arow = Af + r0 * 132;
        const float* Bc   = Bs + c0;
#pragma unroll 2
        for (int k = 0; k < 128; k++) gemm_step<132>(Arow, Bc + k * 128, k, acc);
    }

    // write afh; form m = b_df*afh into Ms
#pragma unroll
    for (int i = 0; i < 8; i++) {
        if (base + r0 + i < N_ATOMS) {
            ull* arow = (ull*)(g_afh + (size_t)(base + r0 + i) * N_HID + c0);
#pragma unroll
            for (int q = 0; q < 4; q++) arow[q] = acc[i * 4 + q];
        }
    }
    __syncthreads();   // all GEMM1 reads of Bs done
#pragma unroll
    for (int i = 0; i < 8; i++) {
        ulonglong2 m01, m23;
        m01.x = mul2(acc[i*4+0], pack2(bdf_s[c0+0], bdf_s[c0+1]));
        m01.y = mul2(acc[i*4+1], pack2(bdf_s[c0+2], bdf_s[c0+3]));
        m23.x = mul2(acc[i*4+2], pack2(bdf_s[c0+4], bdf_s[c0+5]));
        m23.y = mul2(acc[i*4+3], pack2(bdf_s[c0+6], bdf_s[c0+7]));
        *(ulonglong2*)(Ms + (r0 + i) * 132 + c0)     = m01;
        *(ulonglong2*)(Ms + (r0 + i) * 132 + c0 + 4) = m23;
    }
    for (int idx = tid; idx < 128 * 32; idx += TPB)
        ((float4*)Bs)[idx] = ((const float4*)W_fc)[idx];
    __syncthreads();

#pragma unroll
    for (int i = 0; i < 32; i++) acc[i] = 0ULL;
    {
        const float* Arow = Ms + r0 * 132;
        const float* Bc   = Bs + c0;
#pragma unroll 2
        for (int k = 0; k < 128; k++) gemm_step<132>(Arow, Bc + k * 128, k, acc);
    }

#pragma unroll
    for (int i = 0; i < 8; i++) {
        if (base + r0 + i < N_ATOMS) {
            float* orow = out + (size_t)(base + r0 + i) * N_EMB + c0;
            const float* af = Af + (r0 + i) * 132 + c0;
#pragma unroll
            for (int q = 0; q < 4; q++) {
                float lo, hi; unpack2(acc[i * 4 + q], lo, hi);
                orow[2 * q]     = af[2 * q]     - fast_tanh(lo);
                orow[2 * q + 1] = af[2 * q + 1] - fast_tanh(hi);
            }
        }
    }
}

// =====================================================================
// Kernel 2 (pairs): per 128-pair tile
//   dh  = distance @ W_df + b_df
//   m   = dh * g_afh[j]
//   msg = tanh(m @ W_fc)
//   sorted-run segment sum over i, atomicAdd per run
// smem: U (dist[128][104] then Ms[128][132]), Bs[128][128]
// =====================================================================
__global__ void __launch_bounds__(TPB, 1) pairs_kernel(
    const float* __restrict__ distance,
    const int*   __restrict__ dmi,
    const int*   __restrict__ dmj,
    const float* __restrict__ W_df,
    const float* __restrict__ W_fc,
    const float* __restrict__ b_df,
    float* __restrict__ out)
{
    extern __shared__ float smem[];
    int*   i_s   = (int*)smem;            // 128
    int*   j_s   = ((int*)smem) + 128;    // 128
    float* bdf_s = smem + 256;            // 128
    float* U     = smem + 384;            // dist[128][104] then Ms[128][132]
    float* Bs    = U + 128 * 132;         // 128 x 128

    const int tid = threadIdx.x;
    const int tx = tid & 15, ty = tid >> 4;
    const int c0 = tx * 8, r0 = ty * 8;
    const int pbase = blockIdx.x * 128;

    if (tid < 128) {
        i_s[tid]   = dmi[pbase + tid];
        j_s[tid]   = dmj[pbase + tid];
        bdf_s[tid] = b_df[tid];
    }
    // distance tile: 128 rows x 25 float4 (stride 104 floats = 26 f4)
    for (int idx = tid; idx < 128 * 25; idx += TPB) {
        int rr = idx / 25, q = idx - rr * 25;
        ((float4*)U)[rr * 26 + q] =
            ((const float4*)distance)[(size_t)pbase * 25 + idx];
    }
    // W_df: 100x128 linear
    for (int idx = tid; idx < 100 * 32; idx += TPB)
        ((float4*)Bs)[idx] = ((const float4*)W_df)[idx];
    __syncthreads();

    ull acc[32];
    {
        ull b[4];
#pragma unroll
        for (int q = 0; q < 4; q++) b[q] = pack2(bdf_s[c0 + 2*q], bdf_s[c0 + 2*q + 1]);
#pragma unroll
        for (int i = 0; i < 8; i++)
#pragma unroll
            for (int q = 0; q < 4; q++) acc[i * 4 + q] = b[q];
    }
    {   // GEMM1: dh = dist @ W_df + b_df   (K = 100, A stride 104)
        const float* Arow = U + r0 * 104;
        const float* Bc   = Bs + c0;
#pragma unroll 2
        for (int k = 0; k < N_DIST; k++) gemm_step<104>(Arow, Bc + k * 128, k, acc);
    }

    // m = dh * afh[j]   (gather, L2-resident table)
#pragma unroll
    for (int i = 0; i < 8; i++) {
        const int j = j_s[r0 + i];
        const ulonglong2* ar = (const ulonglong2*)(g_afh + (size_t)j * N_HID + c0);
        ulonglong2 g01 = ar[0], g23 = ar[1];
        acc[i*4+0] = mul2(acc[i*4+0], g01.x);
        acc[i*4+1] = mul2(acc[i*4+1], g01.y);
        acc[i*4+2] = mul2(acc[i*4+2], g23.x);
        acc[i*4+3] = mul2(acc[i*4+3], g23.y);
    }
    __syncthreads();   // GEMM1 reads of U/Bs complete

    // store m row-major into Ms (stride 132), overwrite Bs with W_fc
#pragma unroll
    for (int i = 0; i < 8; i++) {
        ulonglong2 m01, m23;
        m01.x = acc[i*4+0]; m01.y = acc[i*4+1];
        m23.x = acc[i*4+2]; m23.y = acc[i*4+3];
        *(ulonglong2*)(U + (r0 + i) * 132 + c0)     = m01;
        *(ulonglong2*)(U + (r0 + i) * 132 + c0 + 4) = m23;
    }
    for (int idx = tid; idx < 128 * 32; idx += TPB)
        ((float4*)Bs)[idx] = ((const float4*)W_fc)[idx];
    __syncthreads();

    // GEMM2: pre = m @ W_fc   (K = 128, A stride 132)
#pragma unroll
    for (int i = 0; i < 32; i++) acc[i] = 0ULL;
    {
        const float* Arow = U + r0 * 132;
        const float* Bc   = Bs + c0;
#pragma unroll 2
        for (int k = 0; k < N_HID; k++) gemm_step<132>(Arow, Bc + k * 128, k, acc);
    }
    __syncthreads();   // all GEMM2 reads of U done

    // msg = tanh(pre) -> U (row-major, stride 132)
#pragma unroll
    for (int i = 0; i < 8; i++) {
        float* mrow = U + (r0 + i) * 132 + c0;
#pragma unroll
        for (int q = 0; q < 4; q++) {
            float lo, hi; unpack2(acc[i * 4 + q], lo, hi);
            mrow[2 * q]     = fast_tanh(lo);
            mrow[2 * q + 1] = fast_tanh(hi);
        }
    }
    __syncthreads();

    // Segmented reduction over sorted i: 256 threads = 128 cols x 2 halves.
    {
        const int c  = tid & 127;
        const int h0 = (tid >> 7) << 6;   // 0 or 64
        int   cur = i_s[h0];
        float sum = 0.0f;
        for (int rr = h0; rr < h0 + 64; rr++) {
            int ii = i_s[rr];
            if (ii != cur) {
                atomicAdd(out + (size_t)cur * N_EMB + c, sum);
                cur = ii; sum = 0.0f;
            }
            sum += U[rr * 132 + c];
        }
        atomicAdd(out + (size_t)cur * N_EMB + c, sum);
    }
}

// =====================================================================
extern "C" void kernel_launch(void* const* d_in, const int* in_sizes, int n_in,
                              void* d_out, int out_size)
{
    const float* atom_features = (const float*)d_in[0];
    const float* distance      = (const float*)d_in[1];
    const int*   dmi           = (const int*)d_in[3];
    const int*   dmj           = (const int*)d_in[4];
    const float* W_cf          = (const float*)d_in[5];
    const float* W_df          = (const float*)d_in[6];
    const float* W_fc          = (const float*)d_in[7];
    const float* b_cf          = (const float*)d_in[8];
    const float* b_df          = (const float*)d_in[9];
    float*       out           = (float*)d_out;

    const int smemA = (256 + 128*132 + 128*132 + 128*128) * 4;   // 201728 B
    const int smemP = (384 + 128*132 + 128*128) * 4;             // 134656 B

    cudaFuncSetAttribute(atoms_kernel, cudaFuncAttributeMaxDynamicSharedMemorySize, smemA);
    cudaFuncSetAttribute(pairs_kernel, cudaFuncAttributeMaxDynamicSharedMemorySize, smemP);

    atoms_kernel<<<(N_ATOMS + 127) / 128, TPB, smemA>>>(
        atom_features, W_cf, W_fc, b_cf, b_df, out);
    pairs_kernel<<<N_PAIRS / 128, TPB, smemP>>>(
        distance, dmi, dmj, W_df, W_fc, b_df, out);
}